// round 15
// baseline (speedup 1.0000x reference)
#include <cuda_runtime.h>
#include <cuda_fp16.h>
#include <cstdint>

#define BLK     512
#define M_TILE  256
#define K_DIM   256
#define VOCAB   1024
#define N_Q     32768
#define AV      4096
#define PT_B    144          // tile row pitch bytes (128 data + 16 pad)
#define MARGIN  1.0e-2f

// ---- smem layout (bytes) ----
#define A_OFF     0
#define A_CHUNK_B (256 * PT_B)                // 36864 per k64 chunk
#define B_OFF     (4 * A_CHUNK_B)             // 147456 (A: all 4 chunks resident)
#define B_TILE_B  (128 * PT_B)                // 18432 per buffer
#define SE_OFF    (B_OFF + 2 * B_TILE_B)      // 184320
#define SZF_OFF   (SE_OFF + 4096)             // 188416 (256 floats)
#define CMIN_OFF  (SZF_OFF + 1024)            // 189440 (512 floats)
#define THR_OFF   (CMIN_OFF + 2048)           // 191488 (256 floats)
#define CNT_OFF   (THR_OFF + 1024)            // 192512 (256 ints)
#define CAND_OFF  (CNT_OFF + 1024)            // 193536 (256*16 ints)
#define TOK_OFF   (CAND_OFF + 16384)          // 209920
#define SMEM_BYTES (TOK_OFF + 1024)           // 210944

__device__ unsigned int g_xb[N_Q * 128];      // x as fp16 pairs: [m][kpair]
__device__ unsigned int g_ebB[VOCAB * 128];   // emb as fp16 pairs: [n][kpair]
__device__ float g_se[VOCAB];
__device__ float g_sz[N_Q];

// ---------------- helpers ----------------
__device__ __forceinline__ uint32_t smem_u32(const void* p) {
    uint32_t a;
    asm("{ .reg .u64 t; cvta.to.shared.u64 t, %1; cvt.u32.u64 %0, t; }" : "=r"(a) : "l"(p));
    return a;
}
__device__ __forceinline__ void cpa16(uint32_t dst, const void* src) {
    asm volatile("cp.async.cg.shared.global [%0], [%1], 16;" :: "r"(dst), "l"(src));
}
__device__ __forceinline__ void cp_commit() { asm volatile("cp.async.commit_group;"); }
__device__ __forceinline__ void cp_wait0()  { asm volatile("cp.async.wait_group 0;" ::: "memory"); }

__device__ __forceinline__ void ldsm4(uint32_t& r0, uint32_t& r1, uint32_t& r2, uint32_t& r3,
                                      uint32_t addr) {
    asm volatile("ldmatrix.sync.aligned.m8n8.x4.shared.b16 {%0,%1,%2,%3}, [%4];"
                 : "=r"(r0), "=r"(r1), "=r"(r2), "=r"(r3) : "r"(addr));
}
// fp16 inputs, fp16 accumulators: 2 D regs (4 halves)
__device__ __forceinline__ void mma_f16acc(uint32_t* d, uint32_t a0, uint32_t a1, uint32_t a2,
                                           uint32_t a3, uint32_t b0, uint32_t b1) {
    asm volatile("mma.sync.aligned.m16n8k16.row.col.f16.f16.f16.f16 "
                 "{%0,%1}, {%2,%3,%4,%5}, {%6,%7}, {%0,%1};"
                 : "+r"(d[0]), "+r"(d[1])
                 : "r"(a0), "r"(a1), "r"(a2), "r"(a3), "r"(b0), "r"(b1));
}

__device__ __forceinline__ unsigned pack_f16(float x, float y) {
    return (unsigned)__half_as_ushort(__float2half_rn(x))
         | ((unsigned)__half_as_ushort(__float2half_rn(y)) << 16);
}

// exact-product compensated accumulate: (s,c) += z*z
__device__ __forceinline__ void sq_acc(float z, float& s, float& c) {
    float p = __fmul_rn(z, z);
    float e = fmaf(z, z, -p);
    float t = __fadd_rn(s, p);
    float bb = __fsub_rn(t, s);
    float err = __fadd_rn(__fsub_rn(s, __fsub_rn(t, bb)), __fsub_rn(p, bb));
    s = t;
    c = __fadd_rn(c, __fadd_rn(err, e));
}

__device__ __forceinline__ void top4(float* T, int* N, float v, int n) {
    if (v < T[3]) {
        if (v < T[1]) {
            T[3] = T[2]; N[3] = N[2]; T[2] = T[1]; N[2] = N[1];
            if (v < T[0]) { T[1] = T[0]; N[1] = N[0]; T[0] = v; N[0] = n; }
            else          { T[1] = v;    N[1] = n; }
        } else {
            if (v < T[2]) { T[3] = T[2]; N[3] = N[2]; T[2] = v; N[2] = n; }
            else          { T[3] = v;    N[3] = n; }
        }
    }
}

// ---------------- merged prep (256 threads/block) ----------------
__global__ void prep_all(const float* __restrict__ x, const float* __restrict__ emb) {
    __shared__ float sx[4096];
    __shared__ float scr[512];
    const int tid = threadIdx.x;
    if (blockIdx.x >= 2048) {
        int w = ((blockIdx.x - 2048) * 256 + tid) >> 5;
        int lane = tid & 31;
        if (w >= VOCAB) return;
        const float* row = emb + (size_t)w * K_DIM;
        double s = 0.0;
        #pragma unroll
        for (int h = 0; h < 2; ++h) {
            float4 e = *(const float4*)(row + lane * 4 + h * 128);
            int col = 2 * lane + h * 64;
            g_ebB[w * 128 + col]     = pack_f16(e.x, e.y);
            g_ebB[w * 128 + col + 1] = pack_f16(e.z, e.w);
            s += (double)e.x * e.x + (double)e.y * e.y + (double)e.z * e.z + (double)e.w * e.w;
        }
        #pragma unroll
        for (int off = 16; off; off >>= 1)
            s += __shfl_down_sync(0xffffffffu, s, off);
        if (lane == 0) g_se[w] = (float)s;
        return;
    }
    const int g = blockIdx.x;
    const float4* xb = (const float4*)(x + (size_t)g * AV);
    #pragma unroll
    for (int it = 0; it < 4; ++it)
        *(float4*)(sx + (tid + it * 256) * 4) = xb[tid + it * 256];
    __syncthreads();
    {
        int v = tid & 15, cg = tid >> 4;
        #pragma unroll
        for (int j = 0; j < 8; ++j) {
            int c = cg * 8 + j;
            float za = sx[(2 * c) * 16 + v];
            float zb = sx[(2 * c + 1) * 16 + v];
            g_xb[(size_t)(g * 16 + v) * 128 + c] = pack_f16(za, zb);
        }
    }
    {
        int vv = tid & 15, seg = tid >> 4;
        float s = 0.0f, cc = 0.0f;
        #pragma unroll
        for (int k = 0; k < 16; ++k)
            sq_acc(sx[(seg * 16 + k) * 16 + vv], s, cc);
        scr[(vv * 16 + seg) * 2] = s;
        scr[(vv * 16 + seg) * 2 + 1] = cc;
    }
    __syncthreads();
    if (tid < 16) {
        double tot = 0.0;
        #pragma unroll
        for (int seg = 0; seg < 16; ++seg) {
            tot += (double)scr[(tid * 16 + seg) * 2];
            tot += (double)scr[(tid * 16 + seg) * 2 + 1];
        }
        g_sz[g * 16 + tid] = (float)tot;
    }
}

extern __shared__ unsigned char smem_raw[];

// ---------------- main: coarse fp16 HMMA (f16 acc) + exact fp32 re-rank ----------------
__global__ void __launch_bounds__(BLK, 1)
vq_kernel(const float* __restrict__ x, const float* __restrict__ emb,
          float* __restrict__ out, int out_size) {
    float* se_s  = (float*)(smem_raw + SE_OFF);
    float* szf   = (float*)(smem_raw + SZF_OFF);
    float* cminw = (float*)(smem_raw + CMIN_OFF);
    float* thr_s = (float*)(smem_raw + THR_OFF);
    int*   cnt_s = (int*)(smem_raw + CNT_OFF);
    int*   cand_s = (int*)(smem_raw + CAND_OFF);
    int*   tok_s = (int*)(smem_raw + TOK_OFF);
    const uint32_t sb = smem_u32(smem_raw);

    const int tid = threadIdx.x;
    const int lane = tid & 31, wid = tid >> 5;
    const int mw = (wid & 7) * 32;        // warp m offset (0..224)
    const int half = wid >> 3;            // n half (0/1)
    const int nw = half * 64;
    const int gr = lane >> 2, gc = (lane & 3) * 2;
    const int m0 = blockIdx.x * M_TILE;
    const int bl0 = blockIdx.x * 16;

    // ldmatrix lane address bases (pitch PT_B both tiles)
    const uint32_t aLane = sb + A_OFF
        + (uint32_t)(mw + (lane & 7) + ((lane >> 3) & 1) * 8) * PT_B
        + ((lane >> 4) & 1) * 16;
    const uint32_t bLane = sb + B_OFF
        + (uint32_t)(nw + (lane & 7) + (lane >> 4) * 8) * PT_B
        + ((lane >> 3) & 1) * 16;

    // ---- stage 0 prefetch: A chunk 0 + B(t0,c0) into buf 0
    {
        const int arow = tid >> 1, ah = (tid & 1) * 64;
        const char* asrc = (const char*)g_xb + (size_t)(m0 + arow) * 512 + ah;
        const uint32_t adst = sb + A_OFF + arow * PT_B + ah;
        #pragma unroll
        for (int j = 0; j < 4; ++j) cpa16(adst + j * 16, asrc + j * 16);
        const int brow = tid >> 2, q = tid & 3;
        const char* bsrc = (const char*)g_ebB + (size_t)brow * 512 + q * 32;
        const uint32_t bdst = sb + B_OFF + brow * PT_B + q * 32;
        cpa16(bdst, bsrc); cpa16(bdst + 16, bsrc + 16);
        cp_commit();
    }
    // ---- stage se, sz
    for (int i = tid; i < VOCAB; i += BLK) se_s[i] = g_se[i];
    if (tid < M_TILE) szf[tid] = g_sz[m0 + tid];

    // ---- coarse fold state: f16x2 accumulators (2 regs per m16n8 block)
    uint32_t du[2][8][2];
    #pragma unroll
    for (int mf = 0; mf < 2; ++mf)
        #pragma unroll
        for (int f = 0; f < 8; ++f) { du[mf][f][0] = 0u; du[mf][f][1] = 0u; }
    const float INFV = __int_as_float(0x7f800000);
    float T[4][4]; int N[4][4];
    #pragma unroll
    for (int mp = 0; mp < 4; ++mp)
        #pragma unroll
        for (int i = 0; i < 4; ++i) { T[mp][i] = INFV; N[mp][i] = 0; }

    // ---- main loop: 8 n-tiles x 4 k-chunks
    #pragma unroll 1
    for (int s = 0; s < 32; ++s) {
        cp_wait0();
        __syncthreads();
        const int t = s >> 2, c = s & 3, buf = s & 1;
        // prefetch next stage
        if (s + 1 < 32) {
            const int t2 = (s + 1) >> 2, c2 = (s + 1) & 3;
            if (s + 1 < 4) {   // A chunks: load once, chunk index == stage
                const int arow = tid >> 1, ah = (tid & 1) * 64;
                const char* asrc = (const char*)g_xb + (size_t)(m0 + arow) * 512
                                 + (s + 1) * 128 + ah;
                const uint32_t adst = sb + A_OFF + (s + 1) * A_CHUNK_B + arow * PT_B + ah;
                #pragma unroll
                for (int j = 0; j < 4; ++j) cpa16(adst + j * 16, asrc + j * 16);
            }
            const int brow = tid >> 2, q = tid & 3;
            const char* bsrc = (const char*)g_ebB + (size_t)(t2 * 128 + brow) * 512
                             + c2 * 128 + q * 32;
            const uint32_t bdst = sb + B_OFF + (buf ^ 1) * B_TILE_B + brow * PT_B + q * 32;
            cpa16(bdst, bsrc); cpa16(bdst + 16, bsrc + 16);
            cp_commit();
        }
        // compute: 4 k16 steps; A from resident chunk c, B from buf
        const uint32_t aC = aLane + c * A_CHUNK_B;
        const uint32_t bC = bLane + buf * B_TILE_B;
        #pragma unroll
        for (int kk = 0; kk < 4; ++kk) {
            uint32_t a0[4], a1[4];
            ldsm4(a0[0], a0[1], a0[2], a0[3], aC + kk * 32);
            ldsm4(a1[0], a1[1], a1[2], a1[3], aC + 16 * PT_B + kk * 32);
            #pragma unroll
            for (int fp = 0; fp < 4; ++fp) {
                uint32_t b0, b1, b2, b3;
                ldsm4(b0, b1, b2, b3, bC + fp * (16 * PT_B) + kk * 32);
                mma_f16acc(du[0][2 * fp],     a0[0], a0[1], a0[2], a0[3], b0, b1);
                mma_f16acc(du[0][2 * fp + 1], a0[0], a0[1], a0[2], a0[3], b2, b3);
                mma_f16acc(du[1][2 * fp],     a1[0], a1[1], a1[2], a1[3], b0, b1);
                mma_f16acc(du[1][2 * fp + 1], a1[0], a1[1], a1[2], a1[3], b2, b3);
            }
        }
        // end of n-tile: unpack f16 dots, coarse dist + top4 fold
        if (c == 3) {
            #pragma unroll
            for (int mf = 0; mf < 2; ++mf) {
                #pragma unroll
                for (int f = 0; f < 8; ++f) {
                    const int nn = t * 128 + nw + f * 8 + gc;
                    const float se0 = se_s[nn], se1 = se_s[nn + 1];
                    float2 r0 = __half22float2(*(const __half2*)&du[mf][f][0]); // row gr
                    float2 r1 = __half22float2(*(const __half2*)&du[mf][f][1]); // row gr+8
                    top4(T[mf * 2],     N[mf * 2],     fmaf(-2.0f, r0.x, se0), nn);
                    top4(T[mf * 2],     N[mf * 2],     fmaf(-2.0f, r0.y, se1), nn + 1);
                    top4(T[mf * 2 + 1], N[mf * 2 + 1], fmaf(-2.0f, r1.x, se0), nn);
                    top4(T[mf * 2 + 1], N[mf * 2 + 1], fmaf(-2.0f, r1.y, se1), nn + 1);
                    du[mf][f][0] = 0u; du[mf][f][1] = 0u;
                }
            }
        }
    }

    // ---- coarse min per m-position: quad-reduce over gc lanes, write per half
    #pragma unroll
    for (int mp = 0; mp < 4; ++mp) {
        float v = T[mp][0];
        #pragma unroll
        for (int off = 1; off <= 2; off <<= 1)
            v = fminf(v, __shfl_xor_sync(0xffffffffu, v, off));
        if ((lane & 3) == 0)
            cminw[half * 256 + mw + (mp >> 1) * 16 + gr + (mp & 1) * 8] = v;
    }
    __syncthreads();
    if (tid < M_TILE) {
        thr_s[tid] = fminf(cminw[tid], cminw[256 + tid]) + MARGIN;
        cnt_s[tid] = 0;
    }
    __syncthreads();
    // ---- append candidates: pass 1 = per-thread best (guaranteed capture, <=8/query)
    #pragma unroll
    for (int mp = 0; mp < 4; ++mp) {
        const int mloc = mw + (mp >> 1) * 16 + gr + (mp & 1) * 8;
        if (T[mp][0] <= thr_s[mloc]) {
            int pos = atomicAdd(&cnt_s[mloc], 1);
            if (pos < 16) cand_s[mloc * 16 + pos] = N[mp][0];
        }
    }
    __syncthreads();
    // ---- pass 2: remaining candidates within margin
    #pragma unroll
    for (int mp = 0; mp < 4; ++mp) {
        const int mloc = mw + (mp >> 1) * 16 + gr + (mp & 1) * 8;
        const float th = thr_s[mloc];
        #pragma unroll
        for (int i = 1; i < 4; ++i) {
            if (T[mp][i] <= th) {
                int pos = atomicAdd(&cnt_s[mloc], 1);
                if (pos < 16) cand_s[mloc * 16 + pos] = N[mp][i];
            }
        }
    }
    __syncthreads();

    // ---- exact fp32 re-rank (thread per m row), ref rounding chain + index tie-break
    if (tid < M_TILE) {
        const int mg = m0 + tid;
        const float* xr = x + (size_t)(mg >> 4) * AV + (mg & 15);
        const float szm = szf[tid];
        int nc = cnt_s[tid]; if (nc > 16) nc = 16;
        float bestD = INFV; int bestN = 0x7fffffff;
        for (int i = 0; i < nc; ++i) {
            const int n = cand_s[tid * 16 + i];
            const float* er = emb + (size_t)n * K_DIM;
            float p0 = 0.f, p1 = 0.f, p2 = 0.f, p3 = 0.f;
            #pragma unroll 4
            for (int a = 0; a < K_DIM; a += 4) {
                p0 = fmaf(xr[(a + 0) * 16], er[a + 0], p0);
                p1 = fmaf(xr[(a + 1) * 16], er[a + 1], p1);
                p2 = fmaf(xr[(a + 2) * 16], er[a + 2], p2);
                p3 = fmaf(xr[(a + 3) * 16], er[a + 3], p3);
            }
            const float dot = __fadd_rn(__fadd_rn(p0, p1), __fadd_rn(p2, p3));
            const float tv = __fadd_rn(szm, se_s[n]);   // fl(sz + se)
            const float dist = fmaf(-2.0f, dot, tv);    // == fl(t - fl(2*dot))
            if (dist < bestD || (dist == bestD && n < bestN)) { bestD = dist; bestN = n; }
        }
        tok_s[tid] = bestN;
    }
    __syncthreads();

    // ---- outputs: z_q | decoder_input | tokens (as float), guarded by out_size
    float* out_zq  = out;
    float* out_dec = out + (size_t)N_Q * K_DIM;
    float* out_tok = out + (size_t)2 * N_Q * K_DIM;
    const long long need_dec = 2LL * N_Q * K_DIM;
    const bool wd = (long long)out_size >= need_dec;
    const bool wt = (long long)out_size >= need_dec + N_Q;

    if (wt && tid < M_TILE) out_tok[m0 + tid] = (float)tok_s[tid];

    #pragma unroll 1
    for (int g = 0; g < 16; ++g) {
        const float* xr = x + (size_t)(bl0 + g) * AV;
        float* zr = out_zq  + (size_t)(bl0 + g) * AV;
        float* dr = out_dec + (size_t)(bl0 + g) * AV;
        #pragma unroll
        for (int idx = tid * 4; idx < AV; idx += BLK * 4) {
            int a = idx >> 4, v0 = idx & 15;
            float4 xv = *(const float4*)(xr + idx);
            float4 q;
            q.x = emb[(size_t)tok_s[g * 16 + v0 + 0] * K_DIM + a];
            q.y = emb[(size_t)tok_s[g * 16 + v0 + 1] * K_DIM + a];
            q.z = emb[(size_t)tok_s[g * 16 + v0 + 2] * K_DIM + a];
            q.w = emb[(size_t)tok_s[g * 16 + v0 + 3] * K_DIM + a];
            *(float4*)(zr + idx) = q;
            if (wd) {
                float4 dv;
                dv.x = xv.x + (q.x - xv.x);
                dv.y = xv.y + (q.y - xv.y);
                dv.z = xv.z + (q.z - xv.z);
                dv.w = xv.w + (q.w - xv.w);
                *(float4*)(dr + idx) = dv;
            }
        }
    }
}

extern "C" void kernel_launch(void* const* d_in, const int* in_sizes, int n_in,
                              void* d_out, int out_size) {
    const float* x   = (const float*)d_in[0];
    const float* emb = (const float*)d_in[1];
    float* out = (float*)d_out;
    (void)in_sizes; (void)n_in;

    cudaFuncSetAttribute(vq_kernel, cudaFuncAttributeMaxDynamicSharedMemorySize, SMEM_BYTES);

    prep_all<<<2176, 256>>>(x, emb);
    vq_kernel<<<N_Q / M_TILE, BLK, SMEM_BYTES>>>(x, emb, out, out_size);
}

// round 16
// speedup vs baseline: 2.1909x; 2.1909x over previous
#include <cuda_runtime.h>
#include <cuda_bf16.h>
#include <cstdint>

#define BLK     512
#define M_TILE  256
#define K_DIM   256
#define VOCAB   1024
#define N_Q     32768
#define AV      4096
#define PT_B    144          // tile row pitch bytes (128 data + 16 pad)
#define MARGIN  3.2e-4f

// ---- smem layout (bytes) ----
#define A_OFF     0
#define A_CHUNK_B (256 * PT_B)                // 36864 per k64 chunk
#define B_OFF     (4 * A_CHUNK_B)             // 147456 (A: all 4 chunks resident)
#define B_TILE_B  (128 * PT_B)                // 18432 per buffer
#define SE_OFF    (B_OFF + 2 * B_TILE_B)      // 184320
#define SZF_OFF   (SE_OFF + 4096)             // 188416 (256 floats)
#define CMIN_OFF  (SZF_OFF + 1024)            // 189440 (512 floats)
#define THR_OFF   (CMIN_OFF + 2048)           // 191488 (256 floats)
#define CNT_OFF   (THR_OFF + 1024)            // 192512 (256 ints)
#define CAND_OFF  (CNT_OFF + 1024)            // 193536 (256*12 ints)
#define TOK_OFF   (CAND_OFF + 12288)          // 205824
#define SMEM_BYTES (TOK_OFF + 1024)           // 206848

__device__ unsigned int g_xb[N_Q * 128];      // x as bf16 pairs: [m][kpair]
__device__ unsigned int g_ebB[VOCAB * 128];   // emb as bf16 pairs: [n][kpair]
__device__ float g_se[VOCAB];
__device__ float g_sz[N_Q];

// ---------------- helpers ----------------
__device__ __forceinline__ uint32_t smem_u32(const void* p) {
    uint32_t a;
    asm("{ .reg .u64 t; cvta.to.shared.u64 t, %1; cvt.u32.u64 %0, t; }" : "=r"(a) : "l"(p));
    return a;
}
__device__ __forceinline__ void cpa16(uint32_t dst, const void* src) {
    asm volatile("cp.async.cg.shared.global [%0], [%1], 16;" :: "r"(dst), "l"(src));
}
__device__ __forceinline__ void cp_commit() { asm volatile("cp.async.commit_group;"); }
__device__ __forceinline__ void cp_wait0()  { asm volatile("cp.async.wait_group 0;" ::: "memory"); }

__device__ __forceinline__ void ldsm4(uint32_t& r0, uint32_t& r1, uint32_t& r2, uint32_t& r3,
                                      uint32_t addr) {
    asm volatile("ldmatrix.sync.aligned.m8n8.x4.shared.b16 {%0,%1,%2,%3}, [%4];"
                 : "=r"(r0), "=r"(r1), "=r"(r2), "=r"(r3) : "r"(addr));
}
__device__ __forceinline__ void mma_bf16(float* d, uint32_t a0, uint32_t a1, uint32_t a2,
                                         uint32_t a3, uint32_t b0, uint32_t b1) {
    asm volatile("mma.sync.aligned.m16n8k16.row.col.f32.bf16.bf16.f32 "
                 "{%0,%1,%2,%3}, {%4,%5,%6,%7}, {%8,%9}, {%0,%1,%2,%3};"
                 : "+f"(d[0]), "+f"(d[1]), "+f"(d[2]), "+f"(d[3])
                 : "r"(a0), "r"(a1), "r"(a2), "r"(a3), "r"(b0), "r"(b1));
}

__device__ __forceinline__ unsigned pack_bf16(float x, float y) {
    return (unsigned)__bfloat16_as_ushort(__float2bfloat16(x))
         | ((unsigned)__bfloat16_as_ushort(__float2bfloat16(y)) << 16);
}

// exact-product compensated accumulate: (s,c) += z*z
__device__ __forceinline__ void sq_acc(float z, float& s, float& c) {
    float p = __fmul_rn(z, z);
    float e = fmaf(z, z, -p);
    float t = __fadd_rn(s, p);
    float bb = __fsub_rn(t, s);
    float err = __fadd_rn(__fsub_rn(s, __fsub_rn(t, bb)), __fsub_rn(p, bb));
    s = t;
    c = __fadd_rn(c, __fadd_rn(err, e));
}

__device__ __forceinline__ void top2(float* T, int* N, float v, int n) {
    if (v < T[1]) {
        if (v < T[0]) { T[1] = T[0]; N[1] = N[0]; T[0] = v; N[0] = n; }
        else          { T[1] = v;    N[1] = n; }
    }
}

// ---------------- merged prep (256 threads/block) ----------------
__global__ void prep_all(const float* __restrict__ x, const float* __restrict__ emb) {
    __shared__ float sx[4096];
    __shared__ float scr[512];
    const int tid = threadIdx.x;
    if (blockIdx.x >= 2048) {
        int w = ((blockIdx.x - 2048) * 256 + tid) >> 5;
        int lane = tid & 31;
        if (w >= VOCAB) return;
        const float* row = emb + (size_t)w * K_DIM;
        double s = 0.0;
        #pragma unroll
        for (int h = 0; h < 2; ++h) {
            float4 e = *(const float4*)(row + lane * 4 + h * 128);
            int col = 2 * lane + h * 64;
            g_ebB[w * 128 + col]     = pack_bf16(e.x, e.y);
            g_ebB[w * 128 + col + 1] = pack_bf16(e.z, e.w);
            s += (double)e.x * e.x + (double)e.y * e.y + (double)e.z * e.z + (double)e.w * e.w;
        }
        #pragma unroll
        for (int off = 16; off; off >>= 1)
            s += __shfl_down_sync(0xffffffffu, s, off);
        if (lane == 0) g_se[w] = (float)s;
        return;
    }
    const int g = blockIdx.x;
    const float4* xb = (const float4*)(x + (size_t)g * AV);
    #pragma unroll
    for (int it = 0; it < 4; ++it)
        *(float4*)(sx + (tid + it * 256) * 4) = xb[tid + it * 256];
    __syncthreads();
    {
        int v = tid & 15, cg = tid >> 4;
        #pragma unroll
        for (int j = 0; j < 8; ++j) {
            int c = cg * 8 + j;
            float za = sx[(2 * c) * 16 + v];
            float zb = sx[(2 * c + 1) * 16 + v];
            g_xb[(size_t)(g * 16 + v) * 128 + c] = pack_bf16(za, zb);
        }
    }
    {
        int vv = tid & 15, seg = tid >> 4;
        float s = 0.0f, cc = 0.0f;
        #pragma unroll
        for (int k = 0; k < 16; ++k)
            sq_acc(sx[(seg * 16 + k) * 16 + vv], s, cc);
        scr[(vv * 16 + seg) * 2] = s;
        scr[(vv * 16 + seg) * 2 + 1] = cc;
    }
    __syncthreads();
    if (tid < 16) {
        double tot = 0.0;
        #pragma unroll
        for (int seg = 0; seg < 16; ++seg) {
            tot += (double)scr[(tid * 16 + seg) * 2];
            tot += (double)scr[(tid * 16 + seg) * 2 + 1];
        }
        g_sz[g * 16 + tid] = (float)tot;
    }
}

extern __shared__ unsigned char smem_raw[];

// ---------------- main: coarse bf16 HMMA + exact fp32 re-rank + writeback ----------------
__global__ void __launch_bounds__(BLK, 1)
vq_kernel(const float* __restrict__ x, const float* __restrict__ emb,
          float* __restrict__ out, int out_size) {
    float* se_s  = (float*)(smem_raw + SE_OFF);
    float* szf   = (float*)(smem_raw + SZF_OFF);
    float* cminw = (float*)(smem_raw + CMIN_OFF);
    float* thr_s = (float*)(smem_raw + THR_OFF);
    int*   cnt_s = (int*)(smem_raw + CNT_OFF);
    int*   cand_s = (int*)(smem_raw + CAND_OFF);
    int*   tok_s = (int*)(smem_raw + TOK_OFF);
    const uint32_t sb = smem_u32(smem_raw);

    const int tid = threadIdx.x;
    const int lane = tid & 31, wid = tid >> 5;
    const int mw = (wid & 7) * 32;        // warp m offset (0..224)
    const int half = wid >> 3;            // n half (0/1)
    const int nw = half * 64;
    const int gr = lane >> 2, gc = (lane & 3) * 2;
    const int m0 = blockIdx.x * M_TILE;

    // ldmatrix lane address bases (pitch PT_B both tiles)
    const uint32_t aLane = sb + A_OFF
        + (uint32_t)(mw + (lane & 7) + ((lane >> 3) & 1) * 8) * PT_B
        + ((lane >> 4) & 1) * 16;
    const uint32_t bLane = sb + B_OFF
        + (uint32_t)(nw + (lane & 7) + (lane >> 4) * 8) * PT_B
        + ((lane >> 3) & 1) * 16;

    // ---- stage 0 prefetch: A chunk 0 + B(t0,c0) into buf 0
    {
        const int arow = tid >> 1, ah = (tid & 1) * 64;
        const char* asrc = (const char*)g_xb + (size_t)(m0 + arow) * 512 + ah;
        const uint32_t adst = sb + A_OFF + arow * PT_B + ah;
        #pragma unroll
        for (int j = 0; j < 4; ++j) cpa16(adst + j * 16, asrc + j * 16);
        const int brow = tid >> 2, q = tid & 3;
        const char* bsrc = (const char*)g_ebB + (size_t)brow * 512 + q * 32;
        const uint32_t bdst = sb + B_OFF + brow * PT_B + q * 32;
        cpa16(bdst, bsrc); cpa16(bdst + 16, bsrc + 16);
        cp_commit();
    }
    // ---- stage se, sz
    for (int i = tid; i < VOCAB; i += BLK) se_s[i] = g_se[i];
    if (tid < M_TILE) szf[tid] = g_sz[m0 + tid];

    // ---- coarse fold state: d[mf][f][4], top2 per m-position
    float d[2][8][4];
    #pragma unroll
    for (int mf = 0; mf < 2; ++mf)
        #pragma unroll
        for (int f = 0; f < 8; ++f)
            #pragma unroll
            for (int j = 0; j < 4; ++j) d[mf][f][j] = 0.0f;
    const float INFV = __int_as_float(0x7f800000);
    float T[4][2]; int N[4][2];
    #pragma unroll
    for (int mp = 0; mp < 4; ++mp) { T[mp][0] = INFV; T[mp][1] = INFV; N[mp][0] = 0; N[mp][1] = 0; }

    // ---- main loop: 8 n-tiles x 4 k-chunks
    #pragma unroll 1
    for (int s = 0; s < 32; ++s) {
        cp_wait0();
        __syncthreads();
        const int t = s >> 2, c = s & 3, buf = s & 1;
        // prefetch next stage
        if (s + 1 < 32) {
            const int t2 = (s + 1) >> 2, c2 = (s + 1) & 3;
            if (s + 1 < 4) {   // A chunks: load once, chunk index == stage
                const int arow = tid >> 1, ah = (tid & 1) * 64;
                const char* asrc = (const char*)g_xb + (size_t)(m0 + arow) * 512
                                 + (s + 1) * 128 + ah;
                const uint32_t adst = sb + A_OFF + (s + 1) * A_CHUNK_B + arow * PT_B + ah;
                #pragma unroll
                for (int j = 0; j < 4; ++j) cpa16(adst + j * 16, asrc + j * 16);
            }
            const int brow = tid >> 2, q = tid & 3;
            const char* bsrc = (const char*)g_ebB + (size_t)(t2 * 128 + brow) * 512
                             + c2 * 128 + q * 32;
            const uint32_t bdst = sb + B_OFF + (buf ^ 1) * B_TILE_B + brow * PT_B + q * 32;
            cpa16(bdst, bsrc); cpa16(bdst + 16, bsrc + 16);
            cp_commit();
        }
        // compute: 4 k16 steps; A from resident chunk c, B from buf
        const uint32_t aC = aLane + c * A_CHUNK_B;
        const uint32_t bC = bLane + buf * B_TILE_B;
        #pragma unroll
        for (int kk = 0; kk < 4; ++kk) {
            uint32_t a0[4], a1[4];
            ldsm4(a0[0], a0[1], a0[2], a0[3], aC + kk * 32);
            ldsm4(a1[0], a1[1], a1[2], a1[3], aC + 16 * PT_B + kk * 32);
            #pragma unroll
            for (int fp = 0; fp < 4; ++fp) {
                uint32_t b0, b1, b2, b3;
                ldsm4(b0, b1, b2, b3, bC + fp * (16 * PT_B) + kk * 32);
                mma_bf16(d[0][2 * fp],     a0[0], a0[1], a0[2], a0[3], b0, b1);
                mma_bf16(d[0][2 * fp + 1], a0[0], a0[1], a0[2], a0[3], b2, b3);
                mma_bf16(d[1][2 * fp],     a1[0], a1[1], a1[2], a1[3], b0, b1);
                mma_bf16(d[1][2 * fp + 1], a1[0], a1[1], a1[2], a1[3], b2, b3);
            }
        }
        // end of n-tile: coarse dist (se - 2*dot) + top2 fold
        if (c == 3) {
            #pragma unroll
            for (int mf = 0; mf < 2; ++mf) {
                #pragma unroll
                for (int f = 0; f < 8; ++f) {
                    const int nn = t * 128 + nw + f * 8 + gc;
                    const float se0 = se_s[nn], se1 = se_s[nn + 1];
                    top2(T[mf * 2],     N[mf * 2],     fmaf(-2.0f, d[mf][f][0], se0), nn);
                    top2(T[mf * 2],     N[mf * 2],     fmaf(-2.0f, d[mf][f][1], se1), nn + 1);
                    top2(T[mf * 2 + 1], N[mf * 2 + 1], fmaf(-2.0f, d[mf][f][2], se0), nn);
                    top2(T[mf * 2 + 1], N[mf * 2 + 1], fmaf(-2.0f, d[mf][f][3], se1), nn + 1);
                    d[mf][f][0] = 0.0f; d[mf][f][1] = 0.0f;
                    d[mf][f][2] = 0.0f; d[mf][f][3] = 0.0f;
                }
            }
        }
    }

    // ---- coarse min per m-position: quad-reduce over gc lanes, write per half
    #pragma unroll
    for (int mp = 0; mp < 4; ++mp) {
        float v = T[mp][0];
        #pragma unroll
        for (int off = 1; off <= 2; off <<= 1)
            v = fminf(v, __shfl_xor_sync(0xffffffffu, v, off));
        if ((lane & 3) == 0)
            cminw[half * 256 + mw + (mp >> 1) * 16 + gr + (mp & 1) * 8] = v;
    }
    __syncthreads();
    if (tid < M_TILE) {
        thr_s[tid] = fminf(cminw[tid], cminw[256 + tid]) + MARGIN;
        cnt_s[tid] = 0;
    }
    __syncthreads();
    // ---- append candidates within margin
    #pragma unroll
    for (int mp = 0; mp < 4; ++mp) {
        const int mloc = mw + (mp >> 1) * 16 + gr + (mp & 1) * 8;
        const float th = thr_s[mloc];
        #pragma unroll
        for (int i = 0; i < 2; ++i) {
            if (T[mp][i] <= th) {
                int pos = atomicAdd(&cnt_s[mloc], 1);
                if (pos < 12) cand_s[mloc * 12 + pos] = N[mp][i];
            }
        }
    }
    __syncthreads();

    // ---- exact fp32 re-rank (thread per m row), ref rounding chain + index tie-break
    if (tid < M_TILE) {
        const int mg = m0 + tid;
        const float* xr = x + (size_t)(mg >> 4) * AV + (mg & 15);
        const float szm = szf[tid];
        int nc = cnt_s[tid]; if (nc > 12) nc = 12;
        float bestD = INFV; int bestN = 0x7fffffff;
        for (int i = 0; i < nc; ++i) {
            const int n = cand_s[tid * 12 + i];
            const float* er = emb + (size_t)n * K_DIM;
            float p0 = 0.f, p1 = 0.f, p2 = 0.f, p3 = 0.f;
            #pragma unroll 4
            for (int a = 0; a < K_DIM; a += 4) {
                p0 = fmaf(xr[(a + 0) * 16], er[a + 0], p0);
                p1 = fmaf(xr[(a + 1) * 16], er[a + 1], p1);
                p2 = fmaf(xr[(a + 2) * 16], er[a + 2], p2);
                p3 = fmaf(xr[(a + 3) * 16], er[a + 3], p3);
            }
            const float dot = __fadd_rn(__fadd_rn(p0, p1), __fadd_rn(p2, p3));
            const float tv = __fadd_rn(szm, se_s[n]);   // fl(sz + se)
            const float dist = fmaf(-2.0f, dot, tv);    // == fl(t - fl(2*dot))
            if (dist < bestD || (dist == bestD && n < bestN)) { bestD = dist; bestN = n; }
        }
        tok_s[tid] = bestN;
    }
    __syncthreads();

    // ---- outputs: z_q | decoder_input | tokens (as float), guarded by out_size
    float* out_zq  = out;
    float* out_dec = out + (size_t)N_Q * K_DIM;
    float* out_tok = out + (size_t)2 * N_Q * K_DIM;
    const long long need_dec = 2LL * N_Q * K_DIM;
    const bool wd = (long long)out_size >= need_dec;
    const bool wt = (long long)out_size >= need_dec + N_Q;

    if (wt && tid < M_TILE) out_tok[m0 + tid] = (float)tok_s[tid];

    const int bl0 = blockIdx.x * 16;
    #pragma unroll 1
    for (int g = 0; g < 16; ++g) {
        const float* xr = x + (size_t)(bl0 + g) * AV;
        float* zr = out_zq  + (size_t)(bl0 + g) * AV;
        float* dr = out_dec + (size_t)(bl0 + g) * AV;
        #pragma unroll
        for (int idx = tid * 4; idx < AV; idx += BLK * 4) {
            int a = idx >> 4, v0 = idx & 15;
            float4 xv = *(const float4*)(xr + idx);
            float4 q;
            q.x = emb[(size_t)tok_s[g * 16 + v0 + 0] * K_DIM + a];
            q.y = emb[(size_t)tok_s[g * 16 + v0 + 1] * K_DIM + a];
            q.z = emb[(size_t)tok_s[g * 16 + v0 + 2] * K_DIM + a];
            q.w = emb[(size_t)tok_s[g * 16 + v0 + 3] * K_DIM + a];
            *(float4*)(zr + idx) = q;
            if (wd) {
                float4 dv;
                dv.x = xv.x + (q.x - xv.x);
                dv.y = xv.y + (q.y - xv.y);
                dv.z = xv.z + (q.z - xv.z);
                dv.w = xv.w + (q.w - xv.w);
                *(float4*)(dr + idx) = dv;
            }
        }
    }
}

extern "C" void kernel_launch(void* const* d_in, const int* in_sizes, int n_in,
                              void* d_out, int out_size) {
    const float* x   = (const float*)d_in[0];
    const float* emb = (const float*)d_in[1];
    float* out = (float*)d_out;
    (void)in_sizes; (void)n_in;

    cudaFuncSetAttribute(vq_kernel, cudaFuncAttributeMaxDynamicSharedMemorySize, SMEM_BYTES);

    prep_all<<<2176, 256>>>(x, emb);
    vq_kernel<<<N_Q / M_TILE, BLK, SMEM_BYTES>>>(x, emb, out, out_size);
}